// round 1
// baseline (speedup 1.0000x reference)
#include <cuda_runtime.h>
#include <cuda_bf16.h>

// Problem constants
#define BB 32
#define NN 1024
#define FF 128   // F_IN
#define DD 128   // D = DIM*NUM_HEAD
#define DK 0.08838834764831843f  // 128^{-0.5}

// Scratch (no allocations allowed)
__device__ float g_spart[BB * 8 * FF];   // per-(batch,chunk) partial row sums
__device__ float g_wvec[BB * FF];        // Wq @ ksum per batch
__device__ float g_cbias[BB];            // bq . ksum per batch

// ---------------------------------------------------------------------------
// K1: partial row sums of atom_query. grid = B*8 blocks, 128 threads.
// Block (b, ch) sums rows [ch*128, ch*128+128) of batch b.
// ---------------------------------------------------------------------------
__global__ __launch_bounds__(128) void k_rowsum(const float* __restrict__ aq) {
    int b = blockIdx.x >> 3;
    int ch = blockIdx.x & 7;
    int t = threadIdx.x;          // 0..127
    int c4 = t & 31;              // float4 column index
    int sub = t >> 5;             // warp id 0..3

    const float4* base = reinterpret_cast<const float4*>(aq)
                       + ((size_t)b * NN + (size_t)ch * 128) * (FF / 4);

    float4 acc = make_float4(0.f, 0.f, 0.f, 0.f);
#pragma unroll 4
    for (int i = 0; i < 32; i++) {
        float4 v = base[(sub * 32 + i) * (FF / 4) + c4];
        acc.x += v.x; acc.y += v.y; acc.z += v.z; acc.w += v.w;
    }

    __shared__ float4 sh[4][32];
    sh[sub][c4] = acc;
    __syncthreads();
    if (sub == 0) {
        float4 r = sh[0][c4];
        for (int w = 1; w < 4; w++) {
            float4 v = sh[w][c4];
            r.x += v.x; r.y += v.y; r.z += v.z; r.w += v.w;
        }
        reinterpret_cast<float4*>(&g_spart[((size_t)b * 8 + ch) * FF])[c4] = r;
    }
}

// ---------------------------------------------------------------------------
// K2: per batch: s = sum partials; ksum = s@Wk + N*bk; wvec = Wq@ksum;
//     cbias = bq . ksum.  grid = 32 blocks, 128 threads.
// ---------------------------------------------------------------------------
__global__ __launch_bounds__(128) void k_prep(const float* __restrict__ Wq,
                                              const float* __restrict__ bq,
                                              const float* __restrict__ Wk,
                                              const float* __restrict__ bk) {
    int b = blockIdx.x;
    int t = threadIdx.x;
    int lane = t & 31;
    int warp = t >> 5;

    __shared__ float s_sh[FF];
    __shared__ float ksum_sh[DD];

    // reduce partial sums
    float s = 0.f;
#pragma unroll
    for (int ch = 0; ch < 8; ch++)
        s += g_spart[((size_t)b * 8 + ch) * FF + t];
    s_sh[t] = s;
    __syncthreads();

    // ksum[d] = sum_f s[f] * Wk[f,d] + N*bk[d]   (coalesced across d=t)
    float acc = 0.f;
#pragma unroll 8
    for (int f = 0; f < FF; f++)
        acc += s_sh[f] * Wk[(size_t)f * DD + t];
    ksum_sh[t] = acc + (float)NN * bk[t];
    __syncthreads();

    // wvec[f] = sum_d Wq[f,d] * ksum[d]   (warp-per-row)
    for (int j = 0; j < 32; j++) {
        int f = warp * 32 + j;
        float p = 0.f;
#pragma unroll
        for (int dd = lane; dd < DD; dd += 32)
            p += Wq[(size_t)f * DD + dd] * ksum_sh[dd];
        for (int off = 16; off; off >>= 1)
            p += __shfl_xor_sync(0xffffffffu, p, off);
        if (lane == 0) g_wvec[b * FF + f] = p;
    }

    // cbias = bq . ksum
    if (warp == 0) {
        float p = 0.f;
#pragma unroll
        for (int dd = lane; dd < DD; dd += 32)
            p += bq[dd] * ksum_sh[dd];
        for (int off = 16; off; off >>= 1)
            p += __shfl_xor_sync(0xffffffffu, p, off);
        if (lane == 0) g_cbias[b] = p;
    }
}

// ---------------------------------------------------------------------------
// K3: per-batch fused: agg dots -> softmax -> attn out -> weighted row sum
//     -> context matvec. grid = 32 blocks, 1024 threads (32 warps).
// ---------------------------------------------------------------------------
__global__ __launch_bounds__(1024) void k_main(const float* __restrict__ aq,
                                               const float* __restrict__ mask,
                                               const float* __restrict__ Wv,
                                               const float* __restrict__ bv,
                                               float* __restrict__ out_attn,
                                               float* __restrict__ out_ctx) {
    int b = blockIdx.x;
    int tid = threadIdx.x;
    int lane = tid & 31;
    int warp = tid >> 5;   // 0..31, owns rows [warp*32, warp*32+32)

    __shared__ float agg_sh[NN];            // 4 KB (agg, then reused as w)
    __shared__ float4 tpart4[32][FF / 4];   // 16 KB
    __shared__ float red[32];
    __shared__ float bc[2];                 // max, sum broadcasts
    __shared__ float t_sh[FF];
    __shared__ float wsum_sh;

    const float4* aqb = reinterpret_cast<const float4*>(aq)
                      + (size_t)b * NN * (FF / 4);
    float4 wv4 = reinterpret_cast<const float4*>(&g_wvec[b * FF])[lane];
    float cb = g_cbias[b];

    // ---- Phase A: agg[n] = mask ? DK*(row . wvec + cbias) : -1e9 ----
    for (int j0 = 0; j0 < 32; j0 += 8) {
        float4 vbuf[8];
#pragma unroll
        for (int jj = 0; jj < 8; jj++)
            vbuf[jj] = aqb[(warp * 32 + j0 + jj) * (FF / 4) + lane];
#pragma unroll
        for (int jj = 0; jj < 8; jj++) {
            float d = vbuf[jj].x * wv4.x + vbuf[jj].y * wv4.y
                    + vbuf[jj].z * wv4.z + vbuf[jj].w * wv4.w;
            for (int off = 16; off; off >>= 1)
                d += __shfl_xor_sync(0xffffffffu, d, off);
            int n = warp * 32 + j0 + jj;
            if (lane == 0) {
                float m = mask[(size_t)b * NN + n];
                agg_sh[n] = (m != 0.f) ? (DK * (d + cb)) : -1e9f;
            }
        }
    }
    __syncthreads();

    // ---- Phase B: softmax over n (axis=1), write attn, compute w ----
    float a = agg_sh[tid];
    float mx = a;
    for (int off = 16; off; off >>= 1)
        mx = fmaxf(mx, __shfl_xor_sync(0xffffffffu, mx, off));
    if (lane == 0) red[warp] = mx;
    __syncthreads();
    if (warp == 0) {
        float m2 = red[lane];
        for (int off = 16; off; off >>= 1)
            m2 = fmaxf(m2, __shfl_xor_sync(0xffffffffu, m2, off));
        if (lane == 0) bc[0] = m2;
    }
    __syncthreads();
    mx = bc[0];

    float e = expf(a - mx);
    float ssum = e;
    for (int off = 16; off; off >>= 1)
        ssum += __shfl_xor_sync(0xffffffffu, ssum, off);
    if (lane == 0) red[warp] = ssum;
    __syncthreads();
    if (warp == 0) {
        float s2 = red[lane];
        for (int off = 16; off; off >>= 1)
            s2 += __shfl_xor_sync(0xffffffffu, s2, off);
        if (lane == 0) bc[1] = s2;
    }
    __syncthreads();
    float inv = 1.0f / bc[1];

    float attn = e * inv;
    out_attn[(size_t)b * NN + tid] = attn;
    float w = mask[(size_t)b * NN + tid] * attn;

    // wsum = sum of w
    float ws = w;
    for (int off = 16; off; off >>= 1)
        ws += __shfl_xor_sync(0xffffffffu, ws, off);
    __syncthreads();              // done with red's previous use
    if (lane == 0) red[warp] = ws;
    __syncthreads();
    if (warp == 0) {
        float s2 = red[lane];
        for (int off = 16; off; off >>= 1)
            s2 += __shfl_xor_sync(0xffffffffu, s2, off);
        if (lane == 0) wsum_sh = s2;
    }
    agg_sh[tid] = w;              // reuse as weights (value for tid only; own slot)
    __syncthreads();

    // ---- Phase C: t[f] = sum_n w[n] * aq[b,n,f] ----
    float4 acc = make_float4(0.f, 0.f, 0.f, 0.f);
    for (int j0 = 0; j0 < 32; j0 += 8) {
        float4 vbuf[8];
        float wbuf[8];
#pragma unroll
        for (int jj = 0; jj < 8; jj++) {
            int n = warp * 32 + j0 + jj;
            vbuf[jj] = aqb[n * (FF / 4) + lane];
            wbuf[jj] = agg_sh[n];
        }
#pragma unroll
        for (int jj = 0; jj < 8; jj++) {
            acc.x += wbuf[jj] * vbuf[jj].x;
            acc.y += wbuf[jj] * vbuf[jj].y;
            acc.z += wbuf[jj] * vbuf[jj].z;
            acc.w += wbuf[jj] * vbuf[jj].w;
        }
    }
    tpart4[warp][lane] = acc;
    __syncthreads();

    if (tid < FF) {
        const float* tp = reinterpret_cast<const float*>(tpart4);
        float t = 0.f;
#pragma unroll
        for (int w2 = 0; w2 < 32; w2++)
            t += tp[w2 * FF + tid];
        t_sh[tid] = t;
    }
    __syncthreads();

    // ---- Phase D: context[d] = t @ Wv + wsum * bv ----
    if (tid < DD) {
        float accd = 0.f;
#pragma unroll 8
        for (int f = 0; f < FF; f++)
            accd += t_sh[f] * Wv[(size_t)f * DD + tid];
        out_ctx[(size_t)b * DD + tid] = accd + wsum_sh * bv[tid];
    }
}

// ---------------------------------------------------------------------------
// Inputs (metadata order): atom_query, mask, Wq, bq, Wk, bk, Wv, bv
// Output: attn [B*N] followed by context [B*D], float32.
// ---------------------------------------------------------------------------
extern "C" void kernel_launch(void* const* d_in, const int* in_sizes, int n_in,
                              void* d_out, int out_size) {
    const float* aq   = (const float*)d_in[0];
    const float* mask = (const float*)d_in[1];
    const float* Wq   = (const float*)d_in[2];
    const float* bq   = (const float*)d_in[3];
    const float* Wk   = (const float*)d_in[4];
    const float* bk   = (const float*)d_in[5];
    const float* Wv   = (const float*)d_in[6];
    const float* bv   = (const float*)d_in[7];

    float* out_attn = (float*)d_out;
    float* out_ctx  = out_attn + (size_t)BB * NN;

    k_rowsum<<<BB * 8, 128>>>(aq);
    k_prep<<<BB, 128>>>(Wq, bq, Wk, bk);
    k_main<<<BB, 1024>>>(aq, mask, Wv, bv, out_attn, out_ctx);
}

// round 2
// speedup vs baseline: 1.0779x; 1.0779x over previous
#include <cuda_runtime.h>
#include <cuda_bf16.h>

// Problem constants
#define BB 32
#define NN 1024
#define FF 128   // F_IN
#define DD 128   // D = DIM*NUM_HEAD
#define DK 0.08838834764831843f  // 128^{-0.5}

// Scratch (no allocations allowed)
__device__ float g_spart[BB * 32 * FF];  // per-(batch,chunk32) partial row sums
__device__ float g_wvec[BB * FF];        // Wq @ ksum per batch
__device__ float g_cbias[BB];            // bq . ksum per batch
__device__ float g_agg[BB * NN];         // masked agg logits
__device__ float g_w[BB * NN];           // mask * attn weights
__device__ float g_wsum[BB];             // sum of weights
__device__ float g_tpart[BB * 8 * FF];   // weighted rowsum partials

// ---------------------------------------------------------------------------
// K1: partial row sums. grid = B*32 = 1024 blocks, 128 threads.
// Block (b, ch) sums rows [ch*32, ch*32+32). Each warp: 8 rows, 8 batched LDGs.
// ---------------------------------------------------------------------------
__global__ __launch_bounds__(128) void k_rowsum(const float* __restrict__ aq) {
    int b = blockIdx.x >> 5;
    int ch = blockIdx.x & 31;
    int t = threadIdx.x;
    int c4 = t & 31;
    int sub = t >> 5;   // warp 0..3

    const float4* base = reinterpret_cast<const float4*>(aq)
                       + ((size_t)b * NN + (size_t)ch * 32 + (size_t)sub * 8) * (FF / 4);

    float4 v[8];
#pragma unroll
    for (int i = 0; i < 8; i++)
        v[i] = base[i * (FF / 4) + c4];

    float4 acc = v[0];
#pragma unroll
    for (int i = 1; i < 8; i++) {
        acc.x += v[i].x; acc.y += v[i].y; acc.z += v[i].z; acc.w += v[i].w;
    }

    __shared__ float4 sh[4][32];
    sh[sub][c4] = acc;
    __syncthreads();
    if (sub == 0) {
        float4 r = sh[0][c4];
#pragma unroll
        for (int w = 1; w < 4; w++) {
            float4 x = sh[w][c4];
            r.x += x.x; r.y += x.y; r.z += x.z; r.w += x.w;
        }
        reinterpret_cast<float4*>(&g_spart[((size_t)b * 32 + ch) * FF])[c4] = r;
    }
}

// ---------------------------------------------------------------------------
// K2: per batch: s = sum partials; ksum = s@Wk + N*bk; wvec = Wq@ksum;
//     cbias = bq . ksum.  grid = 32 blocks, 128 threads.
// ---------------------------------------------------------------------------
__global__ __launch_bounds__(128) void k_prep(const float* __restrict__ Wq,
                                              const float* __restrict__ bq,
                                              const float* __restrict__ Wk,
                                              const float* __restrict__ bk) {
    int b = blockIdx.x;
    int t = threadIdx.x;
    int lane = t & 31;
    int warp = t >> 5;

    __shared__ float s_sh[FF];
    __shared__ float ksum_sh[DD];

    float s = 0.f;
#pragma unroll
    for (int ch = 0; ch < 32; ch++)
        s += g_spart[((size_t)b * 32 + ch) * FF + t];
    s_sh[t] = s;
    __syncthreads();

    float acc = 0.f;
#pragma unroll 8
    for (int f = 0; f < FF; f++)
        acc += s_sh[f] * Wk[(size_t)f * DD + t];
    ksum_sh[t] = acc + (float)NN * bk[t];
    __syncthreads();

    for (int j = 0; j < 32; j++) {
        int f = warp * 32 + j;
        float p = 0.f;
#pragma unroll
        for (int dd = lane; dd < DD; dd += 32)
            p += Wq[(size_t)f * DD + dd] * ksum_sh[dd];
        for (int off = 16; off; off >>= 1)
            p += __shfl_xor_sync(0xffffffffu, p, off);
        if (lane == 0) g_wvec[b * FF + f] = p;
    }

    if (warp == 0) {
        float p = 0.f;
#pragma unroll
        for (int dd = lane; dd < DD; dd += 32)
            p += bq[dd] * ksum_sh[dd];
        for (int off = 16; off; off >>= 1)
            p += __shfl_xor_sync(0xffffffffu, p, off);
        if (lane == 0) g_cbias[b] = p;
    }
}

// ---------------------------------------------------------------------------
// K3: agg logits, full chip. grid = B*8 = 256 blocks, 256 threads (8 warps).
// Block (b, ch): rows [ch*128, ch*128+128). Warp handles 16 rows.
// agg[b,n] = mask ? DK*(aq[b,n].wvec[b] + cbias[b]) : -1e9
// ---------------------------------------------------------------------------
__global__ __launch_bounds__(256) void k_agg(const float* __restrict__ aq,
                                             const float* __restrict__ mask) {
    int b = blockIdx.x >> 3;
    int ch = blockIdx.x & 7;
    int lane = threadIdx.x & 31;
    int warp = threadIdx.x >> 5;   // 0..7, owns 16 rows

    int row0 = ch * 128 + warp * 16;
    const float4* aqb = reinterpret_cast<const float4*>(aq)
                      + ((size_t)b * NN + row0) * (FF / 4);
    float4 wv4 = reinterpret_cast<const float4*>(&g_wvec[b * FF])[lane];
    float cb = g_cbias[b];

    for (int j0 = 0; j0 < 16; j0 += 8) {
        float4 v[8];
#pragma unroll
        for (int jj = 0; jj < 8; jj++)
            v[jj] = aqb[(j0 + jj) * (FF / 4) + lane];
#pragma unroll
        for (int jj = 0; jj < 8; jj++) {
            float d = v[jj].x * wv4.x + v[jj].y * wv4.y
                    + v[jj].z * wv4.z + v[jj].w * wv4.w;
            for (int off = 16; off; off >>= 1)
                d += __shfl_xor_sync(0xffffffffu, d, off);
            if (lane == 0) {
                int n = row0 + j0 + jj;
                float m = mask[(size_t)b * NN + n];
                g_agg[(size_t)b * NN + n] = (m != 0.f) ? (DK * (d + cb)) : -1e9f;
            }
        }
    }
}

// ---------------------------------------------------------------------------
// K4: softmax over n per batch. grid = 32, 1024 threads.
// Writes attn output, weights w = mask*attn, and wsum.
// ---------------------------------------------------------------------------
__global__ __launch_bounds__(1024) void k_softmax(const float* __restrict__ mask,
                                                  float* __restrict__ out_attn) {
    int b = blockIdx.x;
    int tid = threadIdx.x;
    int lane = tid & 31;
    int warp = tid >> 5;

    __shared__ float red[32];
    __shared__ float bc[2];

    float a = g_agg[(size_t)b * NN + tid];

    float mx = a;
    for (int off = 16; off; off >>= 1)
        mx = fmaxf(mx, __shfl_xor_sync(0xffffffffu, mx, off));
    if (lane == 0) red[warp] = mx;
    __syncthreads();
    if (warp == 0) {
        float m2 = red[lane];
        for (int off = 16; off; off >>= 1)
            m2 = fmaxf(m2, __shfl_xor_sync(0xffffffffu, m2, off));
        if (lane == 0) bc[0] = m2;
    }
    __syncthreads();
    mx = bc[0];

    float e = expf(a - mx);
    float ssum = e;
    for (int off = 16; off; off >>= 1)
        ssum += __shfl_xor_sync(0xffffffffu, ssum, off);
    if (lane == 0) red[warp] = ssum;
    __syncthreads();
    if (warp == 0) {
        float s2 = red[lane];
        for (int off = 16; off; off >>= 1)
            s2 += __shfl_xor_sync(0xffffffffu, s2, off);
        if (lane == 0) bc[1] = s2;
    }
    __syncthreads();
    float inv = 1.0f / bc[1];

    float attn = e * inv;
    out_attn[(size_t)b * NN + tid] = attn;
    float w = mask[(size_t)b * NN + tid] * attn;
    g_w[(size_t)b * NN + tid] = w;

    float ws = w;
    for (int off = 16; off; off >>= 1)
        ws += __shfl_xor_sync(0xffffffffu, ws, off);
    if (lane == 0) red[warp] = ws;
    __syncthreads();
    if (warp == 0) {
        float s2 = red[lane];
        for (int off = 16; off; off >>= 1)
            s2 += __shfl_xor_sync(0xffffffffu, s2, off);
        if (lane == 0) g_wsum[b] = s2;
    }
}

// ---------------------------------------------------------------------------
// K5: weighted row-sum partials, full chip. grid = B*8, 256 threads.
// Block (b, ch): t_part[f] = sum over 128 rows of w[n]*aq[b,n,f].
// ---------------------------------------------------------------------------
__global__ __launch_bounds__(256) void k_wsumrow(const float* __restrict__ aq) {
    int b = blockIdx.x >> 3;
    int ch = blockIdx.x & 7;
    int lane = threadIdx.x & 31;
    int warp = threadIdx.x >> 5;   // 0..7, owns 16 rows

    int row0 = ch * 128 + warp * 16;
    const float4* aqb = reinterpret_cast<const float4*>(aq)
                      + ((size_t)b * NN + row0) * (FF / 4);
    const float* wp = &g_w[(size_t)b * NN + row0];

    float4 acc = make_float4(0.f, 0.f, 0.f, 0.f);
    for (int j0 = 0; j0 < 16; j0 += 8) {
        float4 v[8];
        float wb[8];
#pragma unroll
        for (int jj = 0; jj < 8; jj++) {
            v[jj] = aqb[(j0 + jj) * (FF / 4) + lane];
            wb[jj] = wp[j0 + jj];
        }
#pragma unroll
        for (int jj = 0; jj < 8; jj++) {
            acc.x += wb[jj] * v[jj].x;
            acc.y += wb[jj] * v[jj].y;
            acc.z += wb[jj] * v[jj].z;
            acc.w += wb[jj] * v[jj].w;
        }
    }

    __shared__ float4 sh[8][32];
    sh[warp][lane] = acc;
    __syncthreads();
    if (warp == 0) {
        float4 r = sh[0][lane];
#pragma unroll
        for (int w = 1; w < 8; w++) {
            float4 x = sh[w][lane];
            r.x += x.x; r.y += x.y; r.z += x.z; r.w += x.w;
        }
        reinterpret_cast<float4*>(&g_tpart[((size_t)b * 8 + ch) * FF])[lane] = r;
    }
}

// ---------------------------------------------------------------------------
// K6: finalize context. grid = 32, 128 threads.
// t = sum partials; context[d] = t@Wv + wsum*bv.
// ---------------------------------------------------------------------------
__global__ __launch_bounds__(128) void k_ctx(const float* __restrict__ Wv,
                                             const float* __restrict__ bv,
                                             float* __restrict__ out_ctx) {
    int b = blockIdx.x;
    int t = threadIdx.x;

    __shared__ float t_sh[FF];
    float s = 0.f;
#pragma unroll
    for (int ch = 0; ch < 8; ch++)
        s += g_tpart[((size_t)b * 8 + ch) * FF + t];
    t_sh[t] = s;
    __syncthreads();

    float acc = 0.f;
#pragma unroll 8
    for (int f = 0; f < FF; f++)
        acc += t_sh[f] * Wv[(size_t)f * DD + t];
    out_ctx[(size_t)b * DD + t] = acc + g_wsum[b] * bv[t];
}

// ---------------------------------------------------------------------------
// Inputs (metadata order): atom_query, mask, Wq, bq, Wk, bk, Wv, bv
// Output: attn [B*N] followed by context [B*D], float32.
// ---------------------------------------------------------------------------
extern "C" void kernel_launch(void* const* d_in, const int* in_sizes, int n_in,
                              void* d_out, int out_size) {
    const float* aq   = (const float*)d_in[0];
    const float* mask = (const float*)d_in[1];
    const float* Wq   = (const float*)d_in[2];
    const float* bq   = (const float*)d_in[3];
    const float* Wk   = (const float*)d_in[4];
    const float* bk   = (const float*)d_in[5];
    const float* Wv   = (const float*)d_in[6];
    const float* bv   = (const float*)d_in[7];

    float* out_attn = (float*)d_out;
    float* out_ctx  = out_attn + (size_t)BB * NN;

    k_rowsum<<<BB * 32, 128>>>(aq);
    k_prep<<<BB, 128>>>(Wq, bq, Wk, bk);
    k_agg<<<BB * 8, 256>>>(aq, mask);
    k_softmax<<<BB, 1024>>>(mask, out_attn);
    k_wsumrow<<<BB * 8, 256>>>(aq);
    k_ctx<<<BB, 128>>>(Wv, bv, out_ctx);
}